// round 3
// baseline (speedup 1.0000x reference)
#include <cuda_runtime.h>
#include <cstdint>

// ---------------------------------------------------------------------------
// Problem constants
// ---------------------------------------------------------------------------
#define N_NODES   10000
#define IN_CH     128
#define OUT_CH    64
#define N_EDGES   320000
#define N_STEP    16        // HEADS*OUT_CH*8/32
#define K_SEL     160000    // N_EDGES/2
#define NC        384       // padded combined-weight columns (336 used)
#define NC_USED   336
#define M_PAD     10048     // 157*64
#define NBINS     65536     // 16-bit radix digits

// ---------------------------------------------------------------------------
// Device scratch (static; no allocations allowed)
// ---------------------------------------------------------------------------
__device__ float g_Wc[IN_CH * NC];          // combined weights  [128][384]
__device__ float g_bc[NC];                  // combined bias
__device__ float g_Y[M_PAD * NC];           // GEMM result       [10048][384]
__device__ float g_beta[N_NODES * N_STEP];  // beta per node     [10000][16]
__device__ float g_betamean[N_NODES];
__device__ float g_val[N_NODES * OUT_CH];   // relu(x@Wv+bv)     [10000][64]
__device__ float g_aew[N_EDGES];

__device__ unsigned long long g_prefix;     // radix-select running prefix / final threshold
__device__ int g_R;                         // remaining rank within candidates
__device__ int g_hist[NBINS];

__device__ int g_count[N_NODES];
__device__ int g_offset[N_NODES + 1];
__device__ int g_cursor[N_NODES];
__device__ int   g_csr_dst[K_SEL];
__device__ float g_csr_w[K_SEL];

// ---------------------------------------------------------------------------
// Composite ordering key: larger value first, ties -> smaller edge id first
// (identical ordering to stable argsort(-aew))
// ---------------------------------------------------------------------------
__device__ __forceinline__ unsigned long long make_key(float f, int e) {
    unsigned u = __float_as_uint(f);
    u = (u & 0x80000000u) ? ~u : (u | 0x80000000u);   // order-preserving map
    return ((unsigned long long)u << 32) | (unsigned)(0xFFFFFFFFu - (unsigned)e);
}

// ---------------------------------------------------------------------------
// K1: build combined weight matrix Wc / bias bc
//   cols [0,256):   Wc[i, s*16+k] = W_inc[i, s*32+k]        (for map_weights dot)
//   cols [256,272): Wc[i, 256+s]  = sum_k W_inc[i,s*32+16+k]*p_t[s,k]
//   cols [272,336): W_value
//   cols [336,384): zero padding
// ---------------------------------------------------------------------------
__global__ void k_prep(const float* __restrict__ W_inc, const float* __restrict__ b_inc,
                       const float* __restrict__ W_value, const float* __restrict__ b_value,
                       const float* __restrict__ p_t) {
    int idx = blockIdx.x * blockDim.x + threadIdx.x;
    if (idx >= IN_CH * NC) return;
    int i = idx / NC;       // fan-in row
    int j = idx % NC;       // combined col
    float v = 0.f, bias = 0.f;
    if (j < 256) {
        int s = j >> 4, k = j & 15;
        v    = W_inc[i * 512 + s * 32 + k];
        bias = b_inc[s * 32 + k];
    } else if (j < 272) {
        int s = j - 256;
        float acc = 0.f, bacc = 0.f;
        #pragma unroll
        for (int k = 0; k < 16; k++) {
            float p = p_t[s * 16 + k];
            acc  += W_inc[i * 512 + s * 32 + 16 + k] * p;
            bacc += b_inc[s * 32 + 16 + k] * p;
        }
        v = acc; bias = bacc;
    } else if (j < NC_USED) {
        int c = j - 272;
        v    = W_value[i * OUT_CH + c];
        bias = b_value[c];
    }
    g_Wc[i * NC + j] = v;
    if (i == 0) g_bc[j] = bias;
}

// ---------------------------------------------------------------------------
// K2: GEMM  Y[10048,384] = x @ Wc + bc
//   64x64 tiles, BK=16, 128 threads, 8x4 microtile; sA transposed (k-major).
//   Row pad 68 (== 0 mod 4) keeps every inner-loop float4 LDS 16B-aligned.
// ---------------------------------------------------------------------------
__global__ void __launch_bounds__(128) k_gemm(const float* __restrict__ x) {
    __shared__ float sA[16][68];   // [k][m]
    __shared__ float sB[16][64];   // [k][n]
    const int n0 = blockIdx.x * 64;
    const int m0 = blockIdx.y * 64;
    const int tid  = threadIdx.x;
    const int trow = tid >> 4;    // 0..7
    const int tcol = tid & 15;    // 0..15
    float acc[8][4];
    #pragma unroll
    for (int i = 0; i < 8; i++)
        #pragma unroll
        for (int j = 0; j < 4; j++) acc[i][j] = 0.f;

    for (int k0 = 0; k0 < IN_CH; k0 += 16) {
        // load A tile (64 m x 16 k): each thread one float4 along k, scatter to sA[k][m]
        #pragma unroll
        for (int i = 0; i < 2; i++) {
            int q  = tid + i * 128;        // 0..255
            int m  = q >> 2;
            int k4 = q & 3;
            float4 v = make_float4(0.f, 0.f, 0.f, 0.f);
            int gm = m0 + m;
            if (gm < N_NODES)
                v = *reinterpret_cast<const float4*>(&x[gm * IN_CH + k0 + k4 * 4]);
            sA[k4 * 4 + 0][m] = v.x;
            sA[k4 * 4 + 1][m] = v.y;
            sA[k4 * 4 + 2][m] = v.z;
            sA[k4 * 4 + 3][m] = v.w;
        }
        // load B tile (16 k x 64 n) as float4
        #pragma unroll
        for (int i = 0; i < 2; i++) {
            int q  = tid + i * 128;
            int k  = q >> 4;
            int n4 = q & 15;
            float4 v = *reinterpret_cast<const float4*>(&g_Wc[(k0 + k) * NC + n0 + n4 * 4]);
            *reinterpret_cast<float4*>(&sB[k][n4 * 4]) = v;
        }
        __syncthreads();
        #pragma unroll
        for (int kk = 0; kk < 16; kk++) {
            float4 a0 = *reinterpret_cast<const float4*>(&sA[kk][trow * 8]);
            float4 a1 = *reinterpret_cast<const float4*>(&sA[kk][trow * 8 + 4]);
            float4 b  = *reinterpret_cast<const float4*>(&sB[kk][tcol * 4]);
            float av[8] = {a0.x, a0.y, a0.z, a0.w, a1.x, a1.y, a1.z, a1.w};
            float bv[4] = {b.x, b.y, b.z, b.w};
            #pragma unroll
            for (int i = 0; i < 8; i++)
                #pragma unroll
                for (int j = 0; j < 4; j++) acc[i][j] += av[i] * bv[j];
        }
        __syncthreads();
    }
    #pragma unroll
    for (int i = 0; i < 8; i++) {
        int gm = m0 + trow * 8 + i;     // < M_PAD always
        #pragma unroll
        for (int j = 0; j < 4; j++) {
            int c = n0 + tcol * 4 + j;
            g_Y[gm * NC + c] = acc[i][j] + g_bc[c];
        }
    }
}

// ---------------------------------------------------------------------------
// K3: epilogue — per node: beta[16], betamean, val[64] (warp per node)
// ---------------------------------------------------------------------------
__global__ void k_epi(const float* __restrict__ mw) {
    int gw   = (blockIdx.x * blockDim.x + threadIdx.x) >> 5;
    int lane = threadIdx.x & 31;
    if (gw >= N_NODES) return;
    const float* y = &g_Y[gw * NC];
    float beta = 0.f;
    if (lane < 16) {
        const float* m = &mw[gw * 16];
        float acc = 0.f;
        #pragma unroll
        for (int k = 0; k < 16; k++) acc += y[lane * 16 + k] * m[k];
        beta = (acc + y[256 + lane]) * (1.0f / 32.0f);
        g_beta[gw * 16 + lane] = beta;
    }
    float s = beta;
    #pragma unroll
    for (int off = 16; off; off >>= 1) s += __shfl_xor_sync(0xffffffffu, s, off);
    if (lane == 0) g_betamean[gw] = s * (1.0f / 16.0f);
    float v0 = y[272 + lane];
    float v1 = y[272 + 32 + lane];
    g_val[gw * 64 + lane]      = v0 > 0.f ? v0 : 0.f;
    g_val[gw * 64 + 32 + lane] = v1 > 0.f ? v1 : 0.f;
}

// ---------------------------------------------------------------------------
// K4: clear all select/CSR state (counts, 64K histogram, prefix/rank)
// ---------------------------------------------------------------------------
__global__ void k_init() {
    int i = blockIdx.x * blockDim.x + threadIdx.x;
    if (i < N_NODES) g_count[i] = 0;
    if (i < NBINS)   g_hist[i] = 0;
    if (i == 0) { g_prefix = 0ull; g_R = K_SEL; }
}

// ---------------------------------------------------------------------------
// K5: first radix pass fused with aew computation:
//   aew[e] = edge_weight[e] * betamean[dst[e]]; histogram top 16 key bits.
// ---------------------------------------------------------------------------
__global__ void k_hist_first(const int* __restrict__ edge_index, const float* __restrict__ ew) {
    int e = blockIdx.x * blockDim.x + threadIdx.x;
    if (e >= N_EDGES) return;
    int dst = edge_index[N_EDGES + e];
    float a = ew[e] * g_betamean[dst];
    g_aew[e] = a;
    unsigned long long key = make_key(a, e);
    atomicAdd(&g_hist[(unsigned)(key >> 48)], 1);
}

// Subsequent passes (pass = 2,1,0): candidates share the accumulated prefix.
__global__ void k_hist(int pass) {
    int e = blockIdx.x * blockDim.x + threadIdx.x;
    if (e >= N_EDGES) return;
    unsigned long long key = make_key(g_aew[e], e);
    if ((key >> (unsigned)((pass + 1) * 16)) == g_prefix) {
        unsigned d = (unsigned)((key >> (unsigned)(pass * 16)) & 0xFFFF);
        atomicAdd(&g_hist[d], 1);
    }
}

// Single block, 1024 threads; thread t owns bins [t*64, t*64+64).
// Finds digit b with  (#keys with digit > b) < R <= (#keys with digit >= b),
// updates prefix/rank, clears its bins for the next pass.
__global__ void __launch_bounds__(1024) k_pick() {
    __shared__ int sh[1024];       // per-thread totals
    __shared__ int suf[1024];      // inclusive suffix sums
    int t = threadIdx.x;
    int base = t * 64;
    int tot = 0;
    int local[64];
    #pragma unroll
    for (int i = 0; i < 64; i++) { local[i] = g_hist[base + i]; tot += local[i]; }
    sh[t] = tot;
    __syncthreads();
    suf[t] = sh[t];
    __syncthreads();
    for (int off = 1; off < 1024; off <<= 1) {
        int v = (t + off < 1024) ? suf[t + off] : 0;
        __syncthreads();
        suf[t] += v;
        __syncthreads();
    }
    int R = g_R;
    int above = (t + 1 < 1024) ? suf[t + 1] : 0;   // keys with digit owned by higher threads
    if (above < R && R <= above + tot) {
        int acc = above;
        for (int i = 63; i >= 0; --i) {
            int c = local[i];
            if (acc + c >= R) {
                g_prefix = (g_prefix << 16) | (unsigned long long)(unsigned)(base + i);
                g_R = R - acc;
                break;
            }
            acc += c;
        }
    }
    #pragma unroll
    for (int i = 0; i < 64; i++) g_hist[base + i] = 0;
}

// ---------------------------------------------------------------------------
// K6: count selected edges per src node (key >= final threshold, exactly K)
// ---------------------------------------------------------------------------
__global__ void k_count(const int* __restrict__ edge_index) {
    int e = blockIdx.x * blockDim.x + threadIdx.x;
    if (e >= N_EDGES) return;
    unsigned long long key = make_key(g_aew[e], e);
    if (key >= g_prefix)
        atomicAdd(&g_count[edge_index[e]], 1);   // src = edge_index[0][e]
}

// ---------------------------------------------------------------------------
// K7: exclusive scan over 10000 counts (single block, 1024 threads)
// ---------------------------------------------------------------------------
__global__ void __launch_bounds__(1024) k_scan() {
    __shared__ int s[1024];
    int tid = threadIdx.x;
    int carry = 0;
    for (int chunk = 0; chunk < 10; ++chunk) {
        int i = chunk * 1024 + tid;
        int v = (i < N_NODES) ? g_count[i] : 0;
        s[tid] = v;
        __syncthreads();
        #pragma unroll
        for (int off = 1; off < 1024; off <<= 1) {
            int t = (tid >= off) ? s[tid - off] : 0;
            __syncthreads();
            s[tid] += t;
            __syncthreads();
        }
        int incl = s[tid];
        if (i < N_NODES) {
            int excl = carry + incl - v;
            g_offset[i] = excl;
            g_cursor[i] = excl;
        }
        int last = s[1023];
        __syncthreads();
        carry += last;
    }
    if (tid == 0) g_offset[N_NODES] = carry;
}

// ---------------------------------------------------------------------------
// K8: scatter selected edges into CSR (grouped by src)
// ---------------------------------------------------------------------------
__global__ void k_scatter(const int* __restrict__ edge_index, const float* __restrict__ ew) {
    int e = blockIdx.x * blockDim.x + threadIdx.x;
    if (e >= N_EDGES) return;
    unsigned long long key = make_key(g_aew[e], e);
    if (key >= g_prefix) {
        int src = edge_index[e];
        int pos = atomicAdd(&g_cursor[src], 1);
        g_csr_dst[pos] = edge_index[N_EDGES + e];
        g_csr_w[pos]   = ew[e];
    }
}

// ---------------------------------------------------------------------------
// K9: per-node softmax + weighted message aggregation (warp per node)
//   out[src,c] = sum_e val[dst_e,c] * exp(beta[dst_e, c/4]*w_e) / (denom + 1e-16)
// ---------------------------------------------------------------------------
__global__ void __launch_bounds__(256) k_spmm(float* __restrict__ out) {
    __shared__ float sden[8][16];
    int gw   = (blockIdx.x * blockDim.x + threadIdx.x) >> 5;
    int wid  = threadIdx.x >> 5;
    int lane = threadIdx.x & 31;
    if (gw >= N_NODES) return;
    int start = g_offset[gw];
    int end   = g_offset[gw + 1];

    // pass 1: softmax denominators for the 16 distinct gamma values
    float part[16];
    #pragma unroll
    for (int s = 0; s < 16; s++) part[s] = 0.f;
    for (int j = start + lane; j < end; j += 32) {
        int dst = g_csr_dst[j];
        float w = g_csr_w[j];
        const float4* bp4 = reinterpret_cast<const float4*>(&g_beta[dst * 16]);
        float bv[16];
        *reinterpret_cast<float4*>(&bv[0])  = bp4[0];
        *reinterpret_cast<float4*>(&bv[4])  = bp4[1];
        *reinterpret_cast<float4*>(&bv[8])  = bp4[2];
        *reinterpret_cast<float4*>(&bv[12]) = bp4[3];
        #pragma unroll
        for (int s = 0; s < 16; s++) part[s] += __expf(bv[s] * w);
    }
    #pragma unroll
    for (int s = 0; s < 16; s++) {
        float v = part[s];
        #pragma unroll
        for (int off = 16; off; off >>= 1) v += __shfl_xor_sync(0xffffffffu, v, off);
        if (lane == 0) sden[wid][s] = v + 1e-16f;
    }
    __syncwarp();

    const int s0 = lane >> 2;
    const int s1 = s0 + 8;
    const float inv_d0 = 1.0f / sden[wid][s0];
    const float inv_d1 = 1.0f / sden[wid][s1];

    // pass 2: accumulate the 64 output columns (2 per lane)
    float acc0 = 0.f, acc1 = 0.f;
    for (int j = start; j < end; j++) {
        int dst = g_csr_dst[j];
        float w = g_csr_w[j];
        float e0 = __expf(g_beta[dst * 16 + s0] * w) * inv_d0;
        float e1 = __expf(g_beta[dst * 16 + s1] * w) * inv_d1;
        acc0 += g_val[dst * 64 + lane]      * e0;
        acc1 += g_val[dst * 64 + 32 + lane] * e1;
    }
    out[gw * 64 + lane]      = acc0;
    out[gw * 64 + 32 + lane] = acc1;
}

// ---------------------------------------------------------------------------
// Launch sequence
// ---------------------------------------------------------------------------
extern "C" void kernel_launch(void* const* d_in, const int* in_sizes, int n_in,
                              void* d_out, int out_size) {
    const float* x        = (const float*)d_in[0];
    const float* p_t      = (const float*)d_in[1];
    const int*   edge_idx = (const int*)  d_in[2];
    const float* ew       = (const float*)d_in[3];
    const float* W_value  = (const float*)d_in[4];
    const float* b_value  = (const float*)d_in[5];
    const float* W_inc    = (const float*)d_in[6];
    const float* b_inc    = (const float*)d_in[7];
    const float* mw       = (const float*)d_in[8];
    float* out = (float*)d_out;

    k_prep<<<(IN_CH * NC + 255) / 256, 256>>>(W_inc, b_inc, W_value, b_value, p_t);
    k_init<<<(NBINS + 255) / 256, 256>>>();
    k_gemm<<<dim3(NC / 64, M_PAD / 64), 128>>>(x);
    k_epi<<<(N_NODES * 32 + 255) / 256, 256>>>(mw);
    k_hist_first<<<(N_EDGES + 255) / 256, 256>>>(edge_idx, ew);
    k_pick<<<1, 1024>>>();
    for (int p = 2; p >= 0; --p) {
        k_hist<<<(N_EDGES + 255) / 256, 256>>>(p);
        k_pick<<<1, 1024>>>();
    }
    k_count<<<(N_EDGES + 255) / 256, 256>>>(edge_idx);
    k_scan<<<1, 1024>>>();
    k_scatter<<<(N_EDGES + 255) / 256, 256>>>(edge_idx, ew);
    k_spmm<<<(N_NODES * 32 + 255) / 256, 256>>>(out);
}

// round 12
// speedup vs baseline: 3.1545x; 3.1545x over previous
#include <cuda_runtime.h>
#include <cstdint>

// ---------------------------------------------------------------------------
// Problem constants
// ---------------------------------------------------------------------------
#define N_NODES   10000
#define IN_CH     128
#define OUT_CH    64
#define N_EDGES   320000
#define N_STEP    16        // HEADS*OUT_CH*8/32
#define K_SEL     160000    // N_EDGES/2
#define NC        384       // padded combined-weight columns (336 used)
#define NC_USED   336
#define M_PAD     10048     // 157*64
#define NBINS     65536     // 16-bit radix digits

// ---------------------------------------------------------------------------
// Device scratch (static; no allocations allowed)
// ---------------------------------------------------------------------------
__device__ float g_Wc[IN_CH * NC];          // combined weights  [128][384]
__device__ float g_bc[NC];                  // combined bias
__device__ float g_Y[M_PAD * NC];           // GEMM result       [10048][384]
__device__ float g_beta[N_NODES * N_STEP];  // beta per node     [10000][16]
__device__ float g_betamean[N_NODES];
__device__ float g_val[N_NODES * OUT_CH];   // relu(x@Wv+bv)     [10000][64]
__device__ float g_aew[N_EDGES];

__device__ unsigned long long g_prefix;     // select prefix / final 64-bit threshold key
__device__ int g_R;                         // remaining rank within candidates
__device__ int g_hist[NBINS];

__device__ int g_cand_n;
__device__ unsigned long long g_cand_key[N_EDGES];
__device__ int g_cand_src[N_EDGES];

__device__ int g_count[N_NODES];
__device__ int g_offset[N_NODES + 1];
__device__ int g_cursor[N_NODES];
__device__ int   g_csr_dst[K_SEL];
__device__ float g_csr_w[K_SEL];

// ---------------------------------------------------------------------------
// Composite ordering key: larger value first, ties -> smaller edge id first
// (identical ordering to stable argsort(-aew); keys are unique)
// ---------------------------------------------------------------------------
__device__ __forceinline__ unsigned long long make_key(float f, int e) {
    unsigned u = __float_as_uint(f);
    u = (u & 0x80000000u) ? ~u : (u | 0x80000000u);   // order-preserving map
    return ((unsigned long long)u << 32) | (unsigned)(0xFFFFFFFFu - (unsigned)e);
}

// ---------------------------------------------------------------------------
// K1: build combined weight matrix Wc / bias bc, and clear select/CSR state.
// ---------------------------------------------------------------------------
__global__ void k_prep(const float* __restrict__ W_inc, const float* __restrict__ b_inc,
                       const float* __restrict__ W_value, const float* __restrict__ b_value,
                       const float* __restrict__ p_t) {
    int idx = blockIdx.x * blockDim.x + threadIdx.x;
    if (idx < N_NODES) g_count[idx] = 0;
    if (idx < NBINS)   g_hist[idx] = 0;
    if (idx == 0) { g_prefix = 0ull; g_R = K_SEL; g_cand_n = 0; }

    if (idx >= IN_CH * NC) return;
    int i = idx / NC;
    int j = idx % NC;
    float v = 0.f, bias = 0.f;
    if (j < 256) {
        int s = j >> 4, k = j & 15;
        v    = W_inc[i * 512 + s * 32 + k];
        bias = b_inc[s * 32 + k];
    } else if (j < 272) {
        int s = j - 256;
        float acc = 0.f, bacc = 0.f;
        #pragma unroll
        for (int k = 0; k < 16; k++) {
            float p = p_t[s * 16 + k];
            acc  += W_inc[i * 512 + s * 32 + 16 + k] * p;
            bacc += b_inc[s * 32 + 16 + k] * p;
        }
        v = acc; bias = bacc;
    } else if (j < NC_USED) {
        int c = j - 272;
        v    = W_value[i * OUT_CH + c];
        bias = b_value[c];
    }
    g_Wc[i * NC + j] = v;
    if (i == 0) g_bc[j] = bias;
}

// ---------------------------------------------------------------------------
// K2: GEMM  Y[10048,384] = x @ Wc + bc (64x64 tiles, BK=16, 128 threads).
// Global->register prefetch of the next K-tile overlaps the FFMA compute.
// ---------------------------------------------------------------------------
__global__ void __launch_bounds__(128) k_gemm(const float* __restrict__ x) {
    __shared__ float sA[16][68];   // [k][m]; pad 68 keeps float4 LDS 16B-aligned
    __shared__ float sB[16][64];   // [k][n]
    const int n0 = blockIdx.x * 64;
    const int m0 = blockIdx.y * 64;
    const int tid  = threadIdx.x;
    const int trow = tid >> 4;
    const int tcol = tid & 15;

    int mA[2], k4A[2], kB[2], n4B[2];
    #pragma unroll
    for (int i = 0; i < 2; i++) {
        int q = tid + i * 128;
        mA[i]  = q >> 2;  k4A[i] = q & 3;
        kB[i]  = q >> 4;  n4B[i] = q & 15;
    }

    float acc[8][4];
    #pragma unroll
    for (int i = 0; i < 8; i++)
        #pragma unroll
        for (int j = 0; j < 4; j++) acc[i][j] = 0.f;

    float4 aR[2], bR[2];
    #pragma unroll
    for (int i = 0; i < 2; i++) {
        int gm = m0 + mA[i];
        aR[i] = (gm < N_NODES)
            ? *reinterpret_cast<const float4*>(&x[gm * IN_CH + k4A[i] * 4])
            : make_float4(0.f, 0.f, 0.f, 0.f);
        bR[i] = *reinterpret_cast<const float4*>(&g_Wc[kB[i] * NC + n0 + n4B[i] * 4]);
    }

    for (int k0 = 0; k0 < IN_CH; k0 += 16) {
        #pragma unroll
        for (int i = 0; i < 2; i++) {
            sA[k4A[i] * 4 + 0][mA[i]] = aR[i].x;
            sA[k4A[i] * 4 + 1][mA[i]] = aR[i].y;
            sA[k4A[i] * 4 + 2][mA[i]] = aR[i].z;
            sA[k4A[i] * 4 + 3][mA[i]] = aR[i].w;
            *reinterpret_cast<float4*>(&sB[kB[i]][n4B[i] * 4]) = bR[i];
        }
        __syncthreads();

        if (k0 + 16 < IN_CH) {
            int kn = k0 + 16;
            #pragma unroll
            for (int i = 0; i < 2; i++) {
                int gm = m0 + mA[i];
                aR[i] = (gm < N_NODES)
                    ? *reinterpret_cast<const float4*>(&x[gm * IN_CH + kn + k4A[i] * 4])
                    : make_float4(0.f, 0.f, 0.f, 0.f);
                bR[i] = *reinterpret_cast<const float4*>(&g_Wc[(kn + kB[i]) * NC + n0 + n4B[i] * 4]);
            }
        }

        #pragma unroll
        for (int kk = 0; kk < 16; kk++) {
            float4 a0 = *reinterpret_cast<const float4*>(&sA[kk][trow * 8]);
            float4 a1 = *reinterpret_cast<const float4*>(&sA[kk][trow * 8 + 4]);
            float4 b  = *reinterpret_cast<const float4*>(&sB[kk][tcol * 4]);
            float av[8] = {a0.x, a0.y, a0.z, a0.w, a1.x, a1.y, a1.z, a1.w};
            float bv[4] = {b.x, b.y, b.z, b.w};
            #pragma unroll
            for (int i = 0; i < 8; i++)
                #pragma unroll
                for (int j = 0; j < 4; j++) acc[i][j] += av[i] * bv[j];
        }
        __syncthreads();
    }
    #pragma unroll
    for (int i = 0; i < 8; i++) {
        int gm = m0 + trow * 8 + i;
        #pragma unroll
        for (int j = 0; j < 4; j++) {
            int c = n0 + tcol * 4 + j;
            g_Y[gm * NC + c] = acc[i][j] + g_bc[c];
        }
    }
}

// ---------------------------------------------------------------------------
// K3: epilogue — per node: beta[16], betamean, val[64] (warp per node).
// h_W slice staged TRANSPOSED (syT[k*17+s]) so the beta dot product's
// fixed-k loads hit 16 consecutive banks (conflict-free).
// ---------------------------------------------------------------------------
__global__ void __launch_bounds__(256) k_epi(const float* __restrict__ mw) {
    __shared__ float syT[8][16 * 17];   // [wid][k*17+s], y[s*16+k] transposed
    __shared__ float sy2[8][16];        // y[256..271]
    __shared__ float smw[8][16];
    int wid  = threadIdx.x >> 5;
    int lane = threadIdx.x & 31;
    int gw = blockIdx.x * 8 + wid;
    if (gw >= N_NODES) return;

    const float4* y4 = reinterpret_cast<const float4*>(&g_Y[gw * NC]);
    #pragma unroll
    for (int i = 0; i < 3; i++) {
        int idx = lane + 32 * i;       // float4 index, need < 68
        if (idx < 64) {
            int s  = idx >> 2;          // 0..15
            int kb = (idx & 3) * 4;     // 0,4,8,12
            float4 v = y4[idx];         // y[s*16+kb .. +3]
            syT[wid][(kb + 0) * 17 + s] = v.x;
            syT[wid][(kb + 1) * 17 + s] = v.y;
            syT[wid][(kb + 2) * 17 + s] = v.z;
            syT[wid][(kb + 3) * 17 + s] = v.w;
        } else if (idx < 68) {
            int j = idx - 64;           // 0..3
            float4 v = y4[idx];         // y[256+4j .. +3]
            sy2[wid][j * 4 + 0] = v.x;
            sy2[wid][j * 4 + 1] = v.y;
            sy2[wid][j * 4 + 2] = v.z;
            sy2[wid][j * 4 + 3] = v.w;
        }
    }
    if (lane < 4)
        reinterpret_cast<float4*>(smw[wid])[lane] =
            reinterpret_cast<const float4*>(&mw[gw * 16])[lane];
    __syncwarp();

    float beta = 0.f;
    if (lane < 16) {
        float acc = 0.f;
        #pragma unroll
        for (int k = 0; k < 16; k++) acc += syT[wid][k * 17 + lane] * smw[wid][k];
        beta = (acc + sy2[wid][lane]) * (1.0f / 32.0f);
        g_beta[gw * 16 + lane] = beta;
    }
    float s = beta;
    #pragma unroll
    for (int off = 16; off; off >>= 1) s += __shfl_xor_sync(0xffffffffu, s, off);
    if (lane == 0) g_betamean[gw] = s * (1.0f / 16.0f);

    const float* y = &g_Y[gw * NC];
    float v0 = y[272 + lane];
    float v1 = y[272 + 32 + lane];
    g_val[gw * 64 + lane]      = v0 > 0.f ? v0 : 0.f;
    g_val[gw * 64 + 32 + lane] = v1 > 0.f ? v1 : 0.f;
}

// ---------------------------------------------------------------------------
// K4: fused aew computation + top-16-bit histogram (4 edges/thread, LDG.128)
// ---------------------------------------------------------------------------
__global__ void k_hist_first(const int* __restrict__ edge_index, const float* __restrict__ ew) {
    int e0 = (blockIdx.x * blockDim.x + threadIdx.x) * 4;
    if (e0 >= N_EDGES) return;
    int4   dst4 = *reinterpret_cast<const int4*>(&edge_index[N_EDGES + e0]);
    float4 ew4  = *reinterpret_cast<const float4*>(&ew[e0]);
    float4 a4;
    a4.x = ew4.x * g_betamean[dst4.x];
    a4.y = ew4.y * g_betamean[dst4.y];
    a4.z = ew4.z * g_betamean[dst4.z];
    a4.w = ew4.w * g_betamean[dst4.w];
    *reinterpret_cast<float4*>(&g_aew[e0]) = a4;
    const float av[4] = {a4.x, a4.y, a4.z, a4.w};
    #pragma unroll
    for (int q = 0; q < 4; q++) {
        unsigned long long key = make_key(av[q], e0 + q);
        atomicAdd(&g_hist[(unsigned)(key >> 48)], 1);
    }
}

// ---------------------------------------------------------------------------
// K5: coalesced single pick over 64K bins.
// ---------------------------------------------------------------------------
__global__ void __launch_bounds__(1024) k_pick1() {
    __shared__ int sgt[1024];
    __shared__ int wsuf[32];
    __shared__ int s_win, s_above;
    __shared__ int sb[64];
    int t = threadIdx.x, lane = t & 31, w = t >> 5;
    sgt[t] = 0;
    __syncthreads();

    // bin b=i*1024+t -> group b/64 = i*16+(t>>6); warp-uniform -> one atomic/warp
    for (int i = 0; i < 64; i++) {
        int v = g_hist[i * 1024 + t];                 // coalesced
        v = __reduce_add_sync(0xffffffffu, v);
        if (lane == 0) atomicAdd(&sgt[i * 16 + (t >> 6)], v);
    }
    __syncthreads();

    int v = sgt[t];
    int sv = v;
    #pragma unroll
    for (int off = 1; off < 32; off <<= 1) {
        int o = __shfl_down_sync(0xffffffffu, sv, off);
        if (lane + off < 32) sv += o;
    }
    if (lane == 0) wsuf[w] = sv;
    __syncthreads();
    if (w == 0) {
        int x = wsuf[lane];
        int xi = x;
        #pragma unroll
        for (int off = 1; off < 32; off <<= 1) {
            int o = __shfl_down_sync(0xffffffffu, xi, off);
            if (lane + off < 32) xi += o;
        }
        wsuf[lane] = xi;
    }
    __syncthreads();

    int R = g_R;
    int suf_incl = sv + (w < 31 ? wsuf[w + 1] : 0);
    int above = suf_incl - v;
    if (above < R && R <= above + v) { s_win = t; s_above = above; }
    __syncthreads();

    int g = s_win;
    if (t < 64) sb[t] = g_hist[g * 64 + t];
    __syncthreads();
    if (t == 0) {
        int acc = s_above;
        for (int i = 63; i >= 0; --i) {
            int c = sb[i];
            if (acc + c >= R) {
                g_prefix = (unsigned long long)(unsigned)(g * 64 + i);
                g_R = R - acc;
                break;
            }
            acc += c;
        }
    }
}

// ---------------------------------------------------------------------------
// K6: full edge pass (4 edges/thread) — count definitely-selected per src,
// buffer boundary-bin candidates.
// ---------------------------------------------------------------------------
__global__ void k_collect(const int* __restrict__ edge_index) {
    int e0 = (blockIdx.x * blockDim.x + threadIdx.x) * 4;
    if (e0 >= N_EDGES) return;
    float4 a4   = *reinterpret_cast<const float4*>(&g_aew[e0]);
    int4   src4 = *reinterpret_cast<const int4*>(&edge_index[e0]);
    const float av[4] = {a4.x, a4.y, a4.z, a4.w};
    const int   sv[4] = {src4.x, src4.y, src4.z, src4.w};
    unsigned b = (unsigned)g_prefix;
    #pragma unroll
    for (int q = 0; q < 4; q++) {
        unsigned long long key = make_key(av[q], e0 + q);
        unsigned hi = (unsigned)(key >> 48);
        if (hi > b) {
            atomicAdd(&g_count[sv[q]], 1);
        } else if (hi == b) {
            int pos = atomicAdd(&g_cand_n, 1);
            g_cand_key[pos] = key;
            g_cand_src[pos] = sv[q];
        }
    }
}

// ---------------------------------------------------------------------------
// K7 (fused): resolve remaining 48 threshold bits, finish counts, scan.
// ---------------------------------------------------------------------------
__global__ void __launch_bounds__(1024) k_thresh_scan() {
    __shared__ int h[256];
    __shared__ unsigned long long sP;
    __shared__ int sR;
    __shared__ int wex[32];
    __shared__ int stot;
    int t = threadIdx.x, lane = t & 31, w = t >> 5;
    if (t == 0) { sP = g_prefix; sR = g_R; }
    __syncthreads();
    int C = g_cand_n;

    for (int p = 5; p >= 0; --p) {
        if (t < 256) h[t] = 0;
        __syncthreads();
        unsigned long long P = sP;
        for (int i = t; i < C; i += 1024) {
            unsigned long long k = g_cand_key[i];
            if ((k >> (unsigned)((p + 1) * 8)) == P)
                atomicAdd(&h[(int)((k >> (unsigned)(p * 8)) & 0xFF)], 1);
        }
        __syncthreads();
        if (t == 0) {
            int R = sR, acc = 0, d = 255;
            for (; d >= 0; --d) {
                int c = h[d];
                if (acc + c >= R) { sR = R - acc; break; }
                acc += c;
            }
            sP = (P << 8) | (unsigned long long)(unsigned)d;
        }
        __syncthreads();
    }
    unsigned long long P = sP;
    if (t == 0) g_prefix = P;

    for (int i = t; i < C; i += 1024) {
        if (g_cand_key[i] >= P)
            atomicAdd(&g_count[g_cand_src[i]], 1);
    }
    __threadfence();
    __syncthreads();

    int base = t * 10;
    int loc[10];
    int s = 0;
    #pragma unroll
    for (int i = 0; i < 10; i++) {
        int idx = base + i;
        int vv = (idx < N_NODES) ? g_count[idx] : 0;
        loc[i] = s;
        s += vv;
    }
    int inc = s;
    #pragma unroll
    for (int off = 1; off < 32; off <<= 1) {
        int o = __shfl_up_sync(0xffffffffu, inc, off);
        if (lane >= off) inc += o;
    }
    if (lane == 31) wex[w] = inc;
    __syncthreads();
    if (w == 0) {
        int x = wex[lane];
        int xi = x;
        #pragma unroll
        for (int off = 1; off < 32; off <<= 1) {
            int o = __shfl_up_sync(0xffffffffu, xi, off);
            if (lane >= off) xi += o;
        }
        wex[lane] = xi - x;
        if (lane == 31) stot = xi;
    }
    __syncthreads();
    int tbase = wex[w] + inc - s;
    #pragma unroll
    for (int i = 0; i < 10; i++) {
        int idx = base + i;
        if (idx < N_NODES) {
            int ex = tbase + loc[i];
            g_offset[idx] = ex;
            g_cursor[idx] = ex;
        }
    }
    if (t == 0) g_offset[N_NODES] = stot;
}

// ---------------------------------------------------------------------------
// K8: scatter selected edges into CSR (4 edges/thread, grouped by src)
// ---------------------------------------------------------------------------
__global__ void k_scatter(const int* __restrict__ edge_index, const float* __restrict__ ew) {
    int e0 = (blockIdx.x * blockDim.x + threadIdx.x) * 4;
    if (e0 >= N_EDGES) return;
    float4 a4   = *reinterpret_cast<const float4*>(&g_aew[e0]);
    int4   src4 = *reinterpret_cast<const int4*>(&edge_index[e0]);
    int4   dst4 = *reinterpret_cast<const int4*>(&edge_index[N_EDGES + e0]);
    float4 ew4  = *reinterpret_cast<const float4*>(&ew[e0]);
    const float av[4] = {a4.x, a4.y, a4.z, a4.w};
    const int   sv[4] = {src4.x, src4.y, src4.z, src4.w};
    const int   dv[4] = {dst4.x, dst4.y, dst4.z, dst4.w};
    const float wv[4] = {ew4.x, ew4.y, ew4.z, ew4.w};
    unsigned long long P = g_prefix;
    #pragma unroll
    for (int q = 0; q < 4; q++) {
        unsigned long long key = make_key(av[q], e0 + q);
        if (key >= P) {
            int pos = atomicAdd(&g_cursor[sv[q]], 1);
            g_csr_dst[pos] = dv[q];
            g_csr_w[pos]   = wv[q];
        }
    }
}

// ---------------------------------------------------------------------------
// K9: per-node softmax + aggregation, SINGLE CSR pass (warp per node).
// out[:,c] = (sum_e val[dst,c]*exp(beta[dst,s]*w)) / (sum_e exp(beta[dst,s]*w) + 1e-16)
// Lanes 0-15 compute the 16 distinct exps per edge and accumulate their own
// denominator; numerator exps distributed by shuffle; divide at the end.
// ---------------------------------------------------------------------------
__global__ void __launch_bounds__(256) k_spmm(float* __restrict__ out) {
    int gw   = (blockIdx.x * blockDim.x + threadIdx.x) >> 5;
    int lane = threadIdx.x & 31;
    if (gw >= N_NODES) return;
    int start = g_offset[gw];
    int end   = g_offset[gw + 1];

    const int s0 = lane >> 2;          // 0..7
    const int s1 = s0 + 8;             // 8..15

    float den  = 0.f;                  // lane<16: denominator for s = lane
    float acc0 = 0.f, acc1 = 0.f;
    for (int j = start; j < end; j++) {
        int dst = g_csr_dst[j];
        float w = g_csr_w[j];
        float t = 0.f;
        if (lane < 16) t = __expf(g_beta[dst * 16 + lane] * w);
        den += t;
        float e0 = __shfl_sync(0xffffffffu, t, s0);
        float e1 = __shfl_sync(0xffffffffu, t, s1);
        acc0 += g_val[dst * 64 + lane]      * e0;
        acc1 += g_val[dst * 64 + 32 + lane] * e1;
    }
    float D0 = __shfl_sync(0xffffffffu, den, s0) + 1e-16f;
    float D1 = __shfl_sync(0xffffffffu, den, s1) + 1e-16f;
    out[gw * 64 + lane]      = acc0 / D0;
    out[gw * 64 + 32 + lane] = acc1 / D1;
}

// ---------------------------------------------------------------------------
// Launch sequence (9 launches)
// ---------------------------------------------------------------------------
extern "C" void kernel_launch(void* const* d_in, const int* in_sizes, int n_in,
                              void* d_out, int out_size) {
    const float* x        = (const float*)d_in[0];
    const float* p_t      = (const float*)d_in[1];
    const int*   edge_idx = (const int*)  d_in[2];
    const float* ew       = (const float*)d_in[3];
    const float* W_value  = (const float*)d_in[4];
    const float* b_value  = (const float*)d_in[5];
    const float* W_inc    = (const float*)d_in[6];
    const float* b_inc    = (const float*)d_in[7];
    const float* mw       = (const float*)d_in[8];
    float* out = (float*)d_out;

    const int EDGE4_BLOCKS = (N_EDGES / 4 + 255) / 256;

    k_prep<<<(NBINS + 255) / 256, 256>>>(W_inc, b_inc, W_value, b_value, p_t);
    k_gemm<<<dim3(NC / 64, M_PAD / 64), 128>>>(x);
    k_epi<<<(N_NODES + 7) / 8, 256>>>(mw);
    k_hist_first<<<EDGE4_BLOCKS, 256>>>(edge_idx, ew);
    k_pick1<<<1, 1024>>>();
    k_collect<<<EDGE4_BLOCKS, 256>>>(edge_idx);
    k_thresh_scan<<<1, 1024>>>();
    k_scatter<<<EDGE4_BLOCKS, 256>>>(edge_idx, ew);
    k_spmm<<<(N_NODES * 32 + 255) / 256, 256>>>(out);
}

// round 13
// speedup vs baseline: 3.1662x; 1.0037x over previous
#include <cuda_runtime.h>
#include <cstdint>

// ---------------------------------------------------------------------------
// Problem constants
// ---------------------------------------------------------------------------
#define N_NODES   10000
#define IN_CH     128
#define OUT_CH    64
#define N_EDGES   320000
#define N_STEP    16        // HEADS*OUT_CH*8/32
#define K_SEL     160000    // N_EDGES/2
#define NC        384       // padded combined-weight columns (336 used)
#define NC_USED   336
#define M_PAD     10048     // 157*64
#define NBINS     65536     // 16-bit radix digits

// ---------------------------------------------------------------------------
// Device scratch (static; no allocations allowed)
// ---------------------------------------------------------------------------
__device__ float g_Wc[IN_CH * NC];          // combined weights  [128][384]
__device__ float g_bc[NC];                  // combined bias
__device__ float g_Y[M_PAD * NC];           // GEMM result       [10048][384]
__device__ float g_beta[N_NODES * N_STEP];  // beta per node     [10000][16]
__device__ float g_betamean[N_NODES];
__device__ float g_val[N_NODES * OUT_CH];   // relu(x@Wv+bv)     [10000][64]
__device__ float g_aew[N_EDGES];

__device__ unsigned long long g_prefix;     // select prefix / final 64-bit threshold key
__device__ int g_R;                         // remaining rank within candidates
__device__ int g_hist[NBINS];

__device__ int g_cand_n;
__device__ unsigned long long g_cand_key[N_EDGES];
__device__ int g_cand_src[N_EDGES];

__device__ int g_count[N_NODES];
__device__ int g_offset[N_NODES + 1];
__device__ int g_cursor[N_NODES];
__device__ int   g_csr_dst[K_SEL];
__device__ float g_csr_w[K_SEL];

// ---------------------------------------------------------------------------
// Composite ordering key: larger value first, ties -> smaller edge id first
// (identical ordering to stable argsort(-aew); keys are unique)
// ---------------------------------------------------------------------------
__device__ __forceinline__ unsigned long long make_key(float f, int e) {
    unsigned u = __float_as_uint(f);
    u = (u & 0x80000000u) ? ~u : (u | 0x80000000u);   // order-preserving map
    return ((unsigned long long)u << 32) | (unsigned)(0xFFFFFFFFu - (unsigned)e);
}

// ---------------------------------------------------------------------------
// K1: build combined weight matrix Wc / bias bc, and clear select/CSR state.
// ---------------------------------------------------------------------------
__global__ void k_prep(const float* __restrict__ W_inc, const float* __restrict__ b_inc,
                       const float* __restrict__ W_value, const float* __restrict__ b_value,
                       const float* __restrict__ p_t) {
    int idx = blockIdx.x * blockDim.x + threadIdx.x;
    if (idx < N_NODES) g_count[idx] = 0;
    if (idx < NBINS)   g_hist[idx] = 0;
    if (idx == 0) { g_prefix = 0ull; g_R = K_SEL; g_cand_n = 0; }

    if (idx >= IN_CH * NC) return;
    int i = idx / NC;
    int j = idx % NC;
    float v = 0.f, bias = 0.f;
    if (j < 256) {
        int s = j >> 4, k = j & 15;
        v    = W_inc[i * 512 + s * 32 + k];
        bias = b_inc[s * 32 + k];
    } else if (j < 272) {
        int s = j - 256;
        float acc = 0.f, bacc = 0.f;
        #pragma unroll
        for (int k = 0; k < 16; k++) {
            float p = p_t[s * 16 + k];
            acc  += W_inc[i * 512 + s * 32 + 16 + k] * p;
            bacc += b_inc[s * 32 + 16 + k] * p;
        }
        v = acc; bias = bacc;
    } else if (j < NC_USED) {
        int c = j - 272;
        v    = W_value[i * OUT_CH + c];
        bias = b_value[c];
    }
    g_Wc[i * NC + j] = v;
    if (i == 0) g_bc[j] = bias;
}

// ---------------------------------------------------------------------------
// K2: GEMM  Y[10048,384] = x @ Wc + bc (64x64 tiles, BK=16, 128 threads).
// Global->register prefetch of the next K-tile overlaps the FFMA compute.
// ---------------------------------------------------------------------------
__global__ void __launch_bounds__(128) k_gemm(const float* __restrict__ x) {
    __shared__ float sA[16][68];   // [k][m]; pad 68 keeps float4 LDS 16B-aligned
    __shared__ float sB[16][64];   // [k][n]
    const int n0 = blockIdx.x * 64;
    const int m0 = blockIdx.y * 64;
    const int tid  = threadIdx.x;
    const int trow = tid >> 4;
    const int tcol = tid & 15;

    int mA[2], k4A[2], kB[2], n4B[2];
    #pragma unroll
    for (int i = 0; i < 2; i++) {
        int q = tid + i * 128;
        mA[i]  = q >> 2;  k4A[i] = q & 3;
        kB[i]  = q >> 4;  n4B[i] = q & 15;
    }

    float acc[8][4];
    #pragma unroll
    for (int i = 0; i < 8; i++)
        #pragma unroll
        for (int j = 0; j < 4; j++) acc[i][j] = 0.f;

    float4 aR[2], bR[2];
    #pragma unroll
    for (int i = 0; i < 2; i++) {
        int gm = m0 + mA[i];
        aR[i] = (gm < N_NODES)
            ? *reinterpret_cast<const float4*>(&x[gm * IN_CH + k4A[i] * 4])
            : make_float4(0.f, 0.f, 0.f, 0.f);
        bR[i] = *reinterpret_cast<const float4*>(&g_Wc[kB[i] * NC + n0 + n4B[i] * 4]);
    }

    for (int k0 = 0; k0 < IN_CH; k0 += 16) {
        #pragma unroll
        for (int i = 0; i < 2; i++) {
            sA[k4A[i] * 4 + 0][mA[i]] = aR[i].x;
            sA[k4A[i] * 4 + 1][mA[i]] = aR[i].y;
            sA[k4A[i] * 4 + 2][mA[i]] = aR[i].z;
            sA[k4A[i] * 4 + 3][mA[i]] = aR[i].w;
            *reinterpret_cast<float4*>(&sB[kB[i]][n4B[i] * 4]) = bR[i];
        }
        __syncthreads();

        if (k0 + 16 < IN_CH) {
            int kn = k0 + 16;
            #pragma unroll
            for (int i = 0; i < 2; i++) {
                int gm = m0 + mA[i];
                aR[i] = (gm < N_NODES)
                    ? *reinterpret_cast<const float4*>(&x[gm * IN_CH + kn + k4A[i] * 4])
                    : make_float4(0.f, 0.f, 0.f, 0.f);
                bR[i] = *reinterpret_cast<const float4*>(&g_Wc[(kn + kB[i]) * NC + n0 + n4B[i] * 4]);
            }
        }

        #pragma unroll
        for (int kk = 0; kk < 16; kk++) {
            float4 a0 = *reinterpret_cast<const float4*>(&sA[kk][trow * 8]);
            float4 a1 = *reinterpret_cast<const float4*>(&sA[kk][trow * 8 + 4]);
            float4 b  = *reinterpret_cast<const float4*>(&sB[kk][tcol * 4]);
            float av[8] = {a0.x, a0.y, a0.z, a0.w, a1.x, a1.y, a1.z, a1.w};
            float bv[4] = {b.x, b.y, b.z, b.w};
            #pragma unroll
            for (int i = 0; i < 8; i++)
                #pragma unroll
                for (int j = 0; j < 4; j++) acc[i][j] += av[i] * bv[j];
        }
        __syncthreads();
    }
    #pragma unroll
    for (int i = 0; i < 8; i++) {
        int gm = m0 + trow * 8 + i;
        #pragma unroll
        for (int j = 0; j < 4; j++) {
            int c = n0 + tcol * 4 + j;
            g_Y[gm * NC + c] = acc[i][j] + g_bc[c];
        }
    }
}

// ---------------------------------------------------------------------------
// K3: epilogue — per node: beta[16], betamean, val[64] (warp per node).
// h_W slice staged TRANSPOSED (syT[k*17+s]) so the beta dot product's
// fixed-k loads hit 16 consecutive banks (conflict-free).
// ---------------------------------------------------------------------------
__global__ void __launch_bounds__(256) k_epi(const float* __restrict__ mw) {
    __shared__ float syT[8][16 * 17];   // [wid][k*17+s], y[s*16+k] transposed
    __shared__ float sy2[8][16];        // y[256..271]
    __shared__ float smw[8][16];
    int wid  = threadIdx.x >> 5;
    int lane = threadIdx.x & 31;
    int gw = blockIdx.x * 8 + wid;
    if (gw >= N_NODES) return;

    const float4* y4 = reinterpret_cast<const float4*>(&g_Y[gw * NC]);
    #pragma unroll
    for (int i = 0; i < 3; i++) {
        int idx = lane + 32 * i;       // float4 index, need < 68
        if (idx < 64) {
            int s  = idx >> 2;          // 0..15
            int kb = (idx & 3) * 4;     // 0,4,8,12
            float4 v = y4[idx];         // y[s*16+kb .. +3]
            syT[wid][(kb + 0) * 17 + s] = v.x;
            syT[wid][(kb + 1) * 17 + s] = v.y;
            syT[wid][(kb + 2) * 17 + s] = v.z;
            syT[wid][(kb + 3) * 17 + s] = v.w;
        } else if (idx < 68) {
            int j = idx - 64;           // 0..3
            float4 v = y4[idx];         // y[256+4j .. +3]
            sy2[wid][j * 4 + 0] = v.x;
            sy2[wid][j * 4 + 1] = v.y;
            sy2[wid][j * 4 + 2] = v.z;
            sy2[wid][j * 4 + 3] = v.w;
        }
    }
    if (lane < 4)
        reinterpret_cast<float4*>(smw[wid])[lane] =
            reinterpret_cast<const float4*>(&mw[gw * 16])[lane];
    __syncwarp();

    float beta = 0.f;
    if (lane < 16) {
        float acc = 0.f;
        #pragma unroll
        for (int k = 0; k < 16; k++) acc += syT[wid][k * 17 + lane] * smw[wid][k];
        beta = (acc + sy2[wid][lane]) * (1.0f / 32.0f);
        g_beta[gw * 16 + lane] = beta;
    }
    float s = beta;
    #pragma unroll
    for (int off = 16; off; off >>= 1) s += __shfl_xor_sync(0xffffffffu, s, off);
    if (lane == 0) g_betamean[gw] = s * (1.0f / 16.0f);

    const float* y = &g_Y[gw * NC];
    float v0 = y[272 + lane];
    float v1 = y[272 + 32 + lane];
    g_val[gw * 64 + lane]      = v0 > 0.f ? v0 : 0.f;
    g_val[gw * 64 + 32 + lane] = v1 > 0.f ? v1 : 0.f;
}

// ---------------------------------------------------------------------------
// K4: fused aew computation + top-16-bit histogram (1 edge/thread — high
// occupancy hides the scattered betamean load + atomic latency).
// ---------------------------------------------------------------------------
__global__ void k_hist_first(const int* __restrict__ edge_index, const float* __restrict__ ew) {
    int e = blockIdx.x * blockDim.x + threadIdx.x;
    if (e >= N_EDGES) return;
    int dst = edge_index[N_EDGES + e];
    float a = ew[e] * g_betamean[dst];
    g_aew[e] = a;
    unsigned long long key = make_key(a, e);
    atomicAdd(&g_hist[(unsigned)(key >> 48)], 1);
}

// ---------------------------------------------------------------------------
// K5: coalesced single pick over 64K bins.
// ---------------------------------------------------------------------------
__global__ void __launch_bounds__(1024) k_pick1() {
    __shared__ int sgt[1024];
    __shared__ int wsuf[32];
    __shared__ int s_win, s_above;
    __shared__ int sb[64];
    int t = threadIdx.x, lane = t & 31, w = t >> 5;
    sgt[t] = 0;
    __syncthreads();

    // bin b=i*1024+t -> group b/64 = i*16+(t>>6); warp-uniform -> one atomic/warp
    for (int i = 0; i < 64; i++) {
        int v = g_hist[i * 1024 + t];                 // coalesced
        v = __reduce_add_sync(0xffffffffu, v);
        if (lane == 0) atomicAdd(&sgt[i * 16 + (t >> 6)], v);
    }
    __syncthreads();

    int v = sgt[t];
    int sv = v;
    #pragma unroll
    for (int off = 1; off < 32; off <<= 1) {
        int o = __shfl_down_sync(0xffffffffu, sv, off);
        if (lane + off < 32) sv += o;
    }
    if (lane == 0) wsuf[w] = sv;
    __syncthreads();
    if (w == 0) {
        int x = wsuf[lane];
        int xi = x;
        #pragma unroll
        for (int off = 1; off < 32; off <<= 1) {
            int o = __shfl_down_sync(0xffffffffu, xi, off);
            if (lane + off < 32) xi += o;
        }
        wsuf[lane] = xi;
    }
    __syncthreads();

    int R = g_R;
    int suf_incl = sv + (w < 31 ? wsuf[w + 1] : 0);
    int above = suf_incl - v;
    if (above < R && R <= above + v) { s_win = t; s_above = above; }
    __syncthreads();

    int g = s_win;
    if (t < 64) sb[t] = g_hist[g * 64 + t];
    __syncthreads();
    if (t == 0) {
        int acc = s_above;
        for (int i = 63; i >= 0; --i) {
            int c = sb[i];
            if (acc + c >= R) {
                g_prefix = (unsigned long long)(unsigned)(g * 64 + i);
                g_R = R - acc;
                break;
            }
            acc += c;
        }
    }
}

// ---------------------------------------------------------------------------
// K6: full edge pass (1 edge/thread) — count definitely-selected per src,
// buffer boundary-bin candidates.
// ---------------------------------------------------------------------------
__global__ void k_collect(const int* __restrict__ edge_index) {
    int e = blockIdx.x * blockDim.x + threadIdx.x;
    if (e >= N_EDGES) return;
    unsigned long long key = make_key(g_aew[e], e);
    unsigned hi = (unsigned)(key >> 48);
    unsigned b  = (unsigned)g_prefix;
    if (hi > b) {
        atomicAdd(&g_count[edge_index[e]], 1);
    } else if (hi == b) {
        int pos = atomicAdd(&g_cand_n, 1);
        g_cand_key[pos] = key;
        g_cand_src[pos] = edge_index[e];
    }
}

// ---------------------------------------------------------------------------
// K7 (fused): resolve remaining 48 threshold bits, finish counts, scan.
// ---------------------------------------------------------------------------
__global__ void __launch_bounds__(1024) k_thresh_scan() {
    __shared__ int h[256];
    __shared__ unsigned long long sP;
    __shared__ int sR;
    __shared__ int wex[32];
    __shared__ int stot;
    int t = threadIdx.x, lane = t & 31, w = t >> 5;
    if (t == 0) { sP = g_prefix; sR = g_R; }
    __syncthreads();
    int C = g_cand_n;

    for (int p = 5; p >= 0; --p) {
        if (t < 256) h[t] = 0;
        __syncthreads();
        unsigned long long P = sP;
        for (int i = t; i < C; i += 1024) {
            unsigned long long k = g_cand_key[i];
            if ((k >> (unsigned)((p + 1) * 8)) == P)
                atomicAdd(&h[(int)((k >> (unsigned)(p * 8)) & 0xFF)], 1);
        }
        __syncthreads();
        if (t == 0) {
            int R = sR, acc = 0, d = 255;
            for (; d >= 0; --d) {
                int c = h[d];
                if (acc + c >= R) { sR = R - acc; break; }
                acc += c;
            }
            sP = (P << 8) | (unsigned long long)(unsigned)d;
        }
        __syncthreads();
    }
    unsigned long long P = sP;
    if (t == 0) g_prefix = P;

    for (int i = t; i < C; i += 1024) {
        if (g_cand_key[i] >= P)
            atomicAdd(&g_count[g_cand_src[i]], 1);
    }
    __threadfence();
    __syncthreads();

    int base = t * 10;
    int loc[10];
    int s = 0;
    #pragma unroll
    for (int i = 0; i < 10; i++) {
        int idx = base + i;
        int vv = (idx < N_NODES) ? g_count[idx] : 0;
        loc[i] = s;
        s += vv;
    }
    int inc = s;
    #pragma unroll
    for (int off = 1; off < 32; off <<= 1) {
        int o = __shfl_up_sync(0xffffffffu, inc, off);
        if (lane >= off) inc += o;
    }
    if (lane == 31) wex[w] = inc;
    __syncthreads();
    if (w == 0) {
        int x = wex[lane];
        int xi = x;
        #pragma unroll
        for (int off = 1; off < 32; off <<= 1) {
            int o = __shfl_up_sync(0xffffffffu, xi, off);
            if (lane >= off) xi += o;
        }
        wex[lane] = xi - x;
        if (lane == 31) stot = xi;
    }
    __syncthreads();
    int tbase = wex[w] + inc - s;
    #pragma unroll
    for (int i = 0; i < 10; i++) {
        int idx = base + i;
        if (idx < N_NODES) {
            int ex = tbase + loc[i];
            g_offset[idx] = ex;
            g_cursor[idx] = ex;
        }
    }
    if (t == 0) g_offset[N_NODES] = stot;
}

// ---------------------------------------------------------------------------
// K8: scatter selected edges into CSR (1 edge/thread, grouped by src)
// ---------------------------------------------------------------------------
__global__ void k_scatter(const int* __restrict__ edge_index, const float* __restrict__ ew) {
    int e = blockIdx.x * blockDim.x + threadIdx.x;
    if (e >= N_EDGES) return;
    unsigned long long key = make_key(g_aew[e], e);
    if (key >= g_prefix) {
        int src = edge_index[e];
        int pos = atomicAdd(&g_cursor[src], 1);
        g_csr_dst[pos] = edge_index[N_EDGES + e];
        g_csr_w[pos]   = ew[e];
    }
}

// ---------------------------------------------------------------------------
// K9: per-node softmax + aggregation, SINGLE CSR pass (warp per node).
// out[:,c] = (sum_e val[dst,c]*exp(beta[dst,s]*w)) / (sum_e exp(beta[dst,s]*w) + 1e-16)
// Lanes 0-15 compute the 16 distinct exps per edge and accumulate their own
// denominator; numerator exps distributed by shuffle; divide at the end.
// ---------------------------------------------------------------------------
__global__ void __launch_bounds__(256) k_spmm(float* __restrict__ out) {
    int gw   = (blockIdx.x * blockDim.x + threadIdx.x) >> 5;
    int lane = threadIdx.x & 31;
    if (gw >= N_NODES) return;
    int start = g_offset[gw];
    int end   = g_offset[gw + 1];

    const int s0 = lane >> 2;          // 0..7
    const int s1 = s0 + 8;             // 8..15

    float den  = 0.f;                  // lane<16: denominator for s = lane
    float acc0 = 0.f, acc1 = 0.f;
    for (int j = start; j < end; j++) {
        int dst = g_csr_dst[j];
        float w = g_csr_w[j];
        float t = 0.f;
        if (lane < 16) t = __expf(g_beta[dst * 16 + lane] * w);
        den += t;
        float e0 = __shfl_sync(0xffffffffu, t, s0);
        float e1 = __shfl_sync(0xffffffffu, t, s1);
        acc0 += g_val[dst * 64 + lane]      * e0;
        acc1 += g_val[dst * 64 + 32 + lane] * e1;
    }
    float D0 = __shfl_sync(0xffffffffu, den, s0) + 1e-16f;
    float D1 = __shfl_sync(0xffffffffu, den, s1) + 1e-16f;
    out[gw * 64 + lane]      = acc0 / D0;
    out[gw * 64 + 32 + lane] = acc1 / D1;
}

// ---------------------------------------------------------------------------
// Launch sequence (9 launches)
// ---------------------------------------------------------------------------
extern "C" void kernel_launch(void* const* d_in, const int* in_sizes, int n_in,
                              void* d_out, int out_size) {
    const float* x        = (const float*)d_in[0];
    const float* p_t      = (const float*)d_in[1];
    const int*   edge_idx = (const int*)  d_in[2];
    const float* ew       = (const float*)d_in[3];
    const float* W_value  = (const float*)d_in[4];
    const float* b_value  = (const float*)d_in[5];
    const float* W_inc    = (const float*)d_in[6];
    const float* b_inc    = (const float*)d_in[7];
    const float* mw       = (const float*)d_in[8];
    float* out = (float*)d_out;

    const int EDGE_BLOCKS = (N_EDGES + 255) / 256;

    k_prep<<<(NBINS + 255) / 256, 256>>>(W_inc, b_inc, W_value, b_value, p_t);
    k_gemm<<<dim3(NC / 64, M_PAD / 64), 128>>>(x);
    k_epi<<<(N_NODES + 7) / 8, 256>>>(mw);
    k_hist_first<<<EDGE_BLOCKS, 256>>>(edge_idx, ew);
    k_pick1<<<1, 1024>>>();
    k_collect<<<EDGE_BLOCKS, 256>>>(edge_idx);
    k_thresh_scan<<<1, 1024>>>();
    k_scatter<<<EDGE_BLOCKS, 256>>>(edge_idx, ew);
    k_spmm<<<(N_NODES * 32 + 255) / 256, 256>>>(out);
}